// round 17
// baseline (speedup 1.0000x reference)
#include <cuda_runtime.h>
#include <cuda_bf16.h>
#include <cstdint>

#define BB 256
#define TT 512
#define II 64
#define HH 512
#define OO 24

#define CLUSTER_NCTAS 8
#define NBLOCKS 128
#define NTHREADS 512
#define BM 16
#define HC 64

// A: [b:16][k2: buf0 h 0..255 | buf1 h 256..511 | x 512..543], stride 548 (==4 mod 32)
// hi matrix then lo matrix
#define SAW 548
#define AHL (16 * SAW)            // 8768 u32 per matrix
// B: [col:64][k2: h 0..255 | x 256..287], stride 292 (==4 mod 32), hi then lo
#define OFF_B (2 * AHL)           // 17536
#define SBW 292
#define BHL (64 * SBW)            // 18688
#define OFF_DR (OFF_B + 2 * BHL)  // 54912 : DR0[64*18], DR1[64*18]
#define OFF_BI (OFF_DR + 2304)    // 57216
#define SMEM_U32 (OFF_BI + 64)    // 57280
#define SMEM_BYTES (SMEM_U32 * 4) // 229120

typedef unsigned int u32;

__device__ __forceinline__ u32 pack2(float x, float y) {
    u32 r;
    asm("{.reg .b16 lo, hi;\n\t"
        "cvt.rn.bf16.f32 lo, %1;\n\t"
        "cvt.rn.bf16.f32 hi, %2;\n\t"
        "mov.b32 %0, {lo, hi};}" : "=r"(r) : "f"(x), "f"(y));
    return r;
}
__device__ __forceinline__ float blo(u32 u) {
    __nv_bfloat16_raw r; r.x = (unsigned short)(u & 0xffffu);
    return __bfloat162float(*(__nv_bfloat16*)&r);
}
__device__ __forceinline__ float bhi(u32 u) {
    __nv_bfloat16_raw r; r.x = (unsigned short)(u >> 16);
    return __bfloat162float(*(__nv_bfloat16*)&r);
}
__device__ __forceinline__ float bf16_rnd(float v) {
    return __bfloat162float(__float2bfloat16_rn(v));
}
__device__ __forceinline__ u32 smem_u32p(const void* p) {
    u32 a;
    asm("{ .reg .u64 t; cvta.to.shared.u64 t, %1; cvt.u32.u64 %0, t; }"
        : "=r"(a) : "l"(p));
    return a;
}
__device__ __forceinline__ void ldsm4(u32& r0, u32& r1, u32& r2, u32& r3, u32 addr) {
    asm volatile("ldmatrix.sync.aligned.m8n8.x4.shared.b16 {%0,%1,%2,%3}, [%4];"
                 : "=r"(r0), "=r"(r1), "=r"(r2), "=r"(r3) : "r"(addr));
}
__device__ __forceinline__ void mma_bf16(float& d0, float& d1, float& d2, float& d3,
                                         u32 a0, u32 a1, u32 a2, u32 a3,
                                         u32 b0, u32 b1) {
    asm("mma.sync.aligned.m16n8k16.row.col.f32.bf16.bf16.f32 "
        "{%0,%1,%2,%3}, {%4,%5,%6,%7}, {%8,%9}, {%0,%1,%2,%3};"
        : "+f"(d0), "+f"(d1), "+f"(d2), "+f"(d3)
        : "r"(a0), "r"(a1), "r"(a2), "r"(a3), "r"(b0), "r"(b1));
}

__global__ void __launch_bounds__(NTHREADS, 1) __cluster_dims__(CLUSTER_NCTAS, 1, 1)
rnn_persistent_kernel(const float* __restrict__ x,
                      const float* __restrict__ W_ih,
                      const float* __restrict__ W_hh,
                      const float* __restrict__ b_ih,
                      const float* __restrict__ b_hh,
                      const float* __restrict__ fc_w,
                      const float* __restrict__ fc_b,
                      float* __restrict__ out)
{
    extern __shared__ u32 sm[];
    float* DR0 = (float*)(sm + OFF_DR);
    float* DR1 = DR0 + 1152;
    float* BI  = (float*)(sm + OFF_BI);

    const int tid  = threadIdx.x;
    const int lane = tid & 31;
    const int warp = tid >> 5;             // 0..15
    const int kq   = warp >> 2;            // K-quarter 0..3
    const int wn2  = warp & 3;             // n16 group 0..3
    const int g    = lane >> 2;
    const int q    = lane & 3;
    const int rank = blockIdx.x & (CLUSTER_NCTAS - 1);
    const int cl   = blockIdx.x >> 3;
    const int b0   = cl * BM;
    const int h0   = rank * HC;

    // ---- init: zero A (both h buffers + x), stage split B, bias ----
    for (int u = tid; u < 2 * AHL; u += NTHREADS) sm[u] = 0;
    for (int u = tid; u < 288 * 64; u += NTHREADS) {
        int n = u & 63, k2 = u >> 6;
        float2 w;
        if (k2 < 256)
            w = *(const float2*)&W_hh[(size_t)(h0 + n) * HH + 2 * k2];
        else
            w = *(const float2*)&W_ih[(size_t)(h0 + n) * II + 2 * (k2 - 256)];
        float xh = bf16_rnd(w.x), yh = bf16_rnd(w.y);
        int word = n * SBW + k2;
        sm[OFF_B + word]       = pack2(w.x, w.y);
        sm[OFF_B + BHL + word] = pack2(w.x - xh, w.y - yh);
    }
    if (tid < 64) BI[tid] = b_ih[h0 + tid] + b_hh[h0 + tid];

    // x_0 staging (x single-buffered at k2 512..543)
    const int xb  = tid >> 5;
    const int xi2 = tid & 31;
    const int xword = xb * SAW + 512 + xi2;
    {
        float2 v = *(const float2*)&x[((size_t)(b0 + xb) * TT + 0) * II + 2 * xi2];
        float xh = bf16_rnd(v.x), yh = bf16_rnd(v.y);
        sm[xword]       = pack2(v.x, v.y);
        sm[AHL + xword] = pack2(v.x - xh, v.y - yh);
    }
    __syncthreads();
    asm volatile("barrier.cluster.arrive.aligned;" ::: "memory");
    asm volatile("barrier.cluster.wait.aligned;"   ::: "memory");

    // mapa peer bases
    u32 mp[8];
    {
        u32 base = smem_u32p(sm);
        #pragma unroll
        for (int p = 0; p < 8; ++p)
            asm("mapa.shared::cluster.u32 %0, %1, %2;"
                : "=r"(mp[p]) : "r"(base), "r"(p));
    }

    // ldmatrix lane base addresses (bytes)
    const int rowsel = (lane & 7) + 8 * ((lane >> 3) & 1);
    const int chunk  = lane >> 4;
    const u32 smbase = smem_u32p(sm);
    const u32 aH = smbase + (u32)(rowsel * (SAW * 4) + chunk * 16);
    const u32 aL = aH + (u32)(AHL * 4);
    const u32 bH = smbase + (u32)(OFF_B * 4 + (16 * wn2 + rowsel) * (SBW * 4) + chunk * 16);
    const u32 bL = bH + (u32)(BHL * 4);

    // DR index for this lane
    const int idx0 = (16 * wn2 + 2 * q) * 18 + g;
    const int idx4 = idx0 + 8 * 18;

    // bias for quarter-0 finalization
    const float bc0 = BI[16 * wn2 + 2 * q];
    const float bc1 = BI[16 * wn2 + 2 * q + 1];
    const float bc2 = BI[16 * wn2 + 8 + 2 * q];
    const float bc3 = BI[16 * wn2 + 8 + 2 * q + 1];

    // publish constants (quarter-0 lanes)
    const int k2o_a = rank * 32 + 8 * wn2 + q;
    const int k2o_b = k2o_a + 4;

    for (int t = 0; t < TT; ++t) {
        const int buf  = t & 1;
        const int bufn = buf ^ 1;

        // prefetch x_{t+1}
        float2 xv = make_float2(0.f, 0.f);
        if (t + 1 < TT)
            xv = *(const float2*)&x[((size_t)(b0 + xb) * TT + (t + 1)) * II + 2 * xi2];

        float d0 = 0.f, d1 = 0.f, d2 = 0.f, d3 = 0.f;
        float d4 = 0.f, d5 = 0.f, d6 = 0.f, d7 = 0.f;

        // ---- MMA: 8 h-slices + 1 x-slice for this K-quarter ----
        #pragma unroll
        for (int j = 0; j < 9; ++j) {
            const u32 oa = (j < 8) ? (u32)(buf * 1024 + (8 * kq + j) * 32)
                                   : (u32)(2048 + kq * 32);
            const u32 ob = (j < 8) ? (u32)((8 * kq + j) * 32)
                                   : (u32)(1024 + kq * 32);
            u32 ah0, ah1, ah2, ah3, al0, al1, al2, al3;
            u32 bh0, bh1, bh2, bh3, bl0, bl1, bl2, bl3;
            ldsm4(ah0, ah1, ah2, ah3, aH + oa);
            ldsm4(al0, al1, al2, al3, aL + oa);
            ldsm4(bh0, bh1, bh2, bh3, bH + ob);
            ldsm4(bl0, bl1, bl2, bl3, bL + ob);
            mma_bf16(d0, d1, d2, d3, ah0, ah1, ah2, ah3, bh0, bh2);
            mma_bf16(d0, d1, d2, d3, ah0, ah1, ah2, ah3, bl0, bl2);
            mma_bf16(d0, d1, d2, d3, al0, al1, al2, al3, bh0, bh2);
            mma_bf16(d4, d5, d6, d7, ah0, ah1, ah2, ah3, bh1, bh3);
            mma_bf16(d4, d5, d6, d7, ah0, ah1, ah2, ah3, bl1, bl3);
            mma_bf16(d4, d5, d6, d7, al0, al1, al2, al3, bh1, bh3);
        }

        // ---- stage 1: quarters 1,3 store partials ----
        if (kq == 1) {
            DR0[idx0] = d0; DR0[idx0 + 18] = d1;
            DR0[idx0 + 8] = d2; DR0[idx0 + 26] = d3;
            DR0[idx4] = d4; DR0[idx4 + 18] = d5;
            DR0[idx4 + 8] = d6; DR0[idx4 + 26] = d7;
        } else if (kq == 3) {
            DR1[idx0] = d0; DR1[idx0 + 18] = d1;
            DR1[idx0 + 8] = d2; DR1[idx0 + 26] = d3;
            DR1[idx4] = d4; DR1[idx4 + 18] = d5;
            DR1[idx4 + 8] = d6; DR1[idx4 + 26] = d7;
        }
        __syncthreads();

        // ---- stage 2: q0 += DR0(q1);  q2 += DR1(q3) then rewrites DR1 ----
        if (kq == 0) {
            d0 += DR0[idx0]; d1 += DR0[idx0 + 18];
            d2 += DR0[idx0 + 8]; d3 += DR0[idx0 + 26];
            d4 += DR0[idx4]; d5 += DR0[idx4 + 18];
            d6 += DR0[idx4 + 8]; d7 += DR0[idx4 + 26];
        } else if (kq == 2) {
            d0 += DR1[idx0]; d1 += DR1[idx0 + 18];
            d2 += DR1[idx0 + 8]; d3 += DR1[idx0 + 26];
            d4 += DR1[idx4]; d5 += DR1[idx4 + 18];
            d6 += DR1[idx4 + 8]; d7 += DR1[idx4 + 26];
            DR1[idx0] = d0; DR1[idx0 + 18] = d1;
            DR1[idx0 + 8] = d2; DR1[idx0 + 26] = d3;
            DR1[idx4] = d4; DR1[idx4 + 18] = d5;
            DR1[idx4 + 8] = d6; DR1[idx4 + 26] = d7;
        }
        // commit x_{t+1} (all MMA reads of x_t precede the sync above)
        if (t + 1 < TT) {
            float xh = bf16_rnd(xv.x), yh = bf16_rnd(xv.y);
            sm[xword]       = pack2(xv.x, xv.y);
            sm[AHL + xword] = pack2(xv.x - xh, xv.y - yh);
        }
        __syncthreads();

        // ---- finalize + publish (quarter 0) ----
        if (kq == 0) {
            d0 += DR1[idx0]; d1 += DR1[idx0 + 18];
            d2 += DR1[idx0 + 8]; d3 += DR1[idx0 + 26];
            d4 += DR1[idx4]; d5 += DR1[idx4 + 18];
            d6 += DR1[idx4 + 8]; d7 += DR1[idx4 + 26];

            float v0 = fmaxf(d0 + bc0, 0.f);
            float v1 = fmaxf(d1 + bc1, 0.f);
            float v2 = fmaxf(d2 + bc0, 0.f);
            float v3 = fmaxf(d3 + bc1, 0.f);
            float v4 = fmaxf(d4 + bc2, 0.f);
            float v5 = fmaxf(d5 + bc3, 0.f);
            float v6 = fmaxf(d6 + bc2, 0.f);
            float v7 = fmaxf(d7 + bc3, 0.f);

            float h0v = bf16_rnd(v0), h1v = bf16_rnd(v1);
            float h2v = bf16_rnd(v2), h3v = bf16_rnd(v3);
            float h4v = bf16_rnd(v4), h5v = bf16_rnd(v5);
            float h6v = bf16_rnd(v6), h7v = bf16_rnd(v7);
            u32 hiA = pack2(v0, v1), loA = pack2(v0 - h0v, v1 - h1v);
            u32 hiB = pack2(v2, v3), loB = pack2(v2 - h2v, v3 - h3v);
            u32 hiC = pack2(v4, v5), loC = pack2(v4 - h4v, v5 - h5v);
            u32 hiD = pack2(v6, v7), loD = pack2(v6 - h6v, v7 - h7v);

            const u32 w1 = (u32)((g * SAW + bufn * 256 + k2o_a) * 4);
            const u32 w2 = (u32)(((g + 8) * SAW + bufn * 256 + k2o_a) * 4);
            const u32 w3 = (u32)((g * SAW + bufn * 256 + k2o_b) * 4);
            const u32 w4 = (u32)(((g + 8) * SAW + bufn * 256 + k2o_b) * 4);
            const u32 LOF = (u32)(AHL * 4);
            #pragma unroll
            for (int p = 0; p < 8; ++p) {
                u32 r = mp[p];
                asm volatile("st.shared::cluster.u32 [%0], %1;" :: "r"(r + w1), "r"(hiA) : "memory");
                asm volatile("st.shared::cluster.u32 [%0], %1;" :: "r"(r + w2), "r"(hiB) : "memory");
                asm volatile("st.shared::cluster.u32 [%0], %1;" :: "r"(r + w3), "r"(hiC) : "memory");
                asm volatile("st.shared::cluster.u32 [%0], %1;" :: "r"(r + w4), "r"(hiD) : "memory");
                asm volatile("st.shared::cluster.u32 [%0], %1;" :: "r"(r + LOF + w1), "r"(loA) : "memory");
                asm volatile("st.shared::cluster.u32 [%0], %1;" :: "r"(r + LOF + w2), "r"(loB) : "memory");
                asm volatile("st.shared::cluster.u32 [%0], %1;" :: "r"(r + LOF + w3), "r"(loC) : "memory");
                asm volatile("st.shared::cluster.u32 [%0], %1;" :: "r"(r + LOF + w4), "r"(loD) : "memory");
            }
        }

        // ---- cluster barrier ----
        asm volatile("barrier.cluster.arrive.aligned;" ::: "memory");
        asm volatile("barrier.cluster.wait.aligned;"   ::: "memory");
    }

    // ---- fused FC epilogue: h_T in buf 0 (k2 0..255) of every CTA ----
    if (rank == 0) {
        const int b = b0 + warp;
        float hv[16];
        #pragma unroll
        for (int i = 0; i < 8; ++i) {
            int k2 = lane + 32 * i;
            int word = warp * SAW + k2;
            u32 uh = sm[word];
            u32 ul = sm[AHL + word];
            hv[2 * i]     = blo(uh) + blo(ul);
            hv[2 * i + 1] = bhi(uh) + bhi(ul);
        }
        for (int o = 0; o < OO; ++o) {
            const float* wrow = fc_w + (size_t)o * HH;
            float s = 0.f;
            #pragma unroll
            for (int i = 0; i < 8; ++i) {
                int k2 = lane + 32 * i;
                float2 wv = *(const float2*)&wrow[2 * k2];
                s = fmaf(hv[2 * i], wv.x, s);
                s = fmaf(hv[2 * i + 1], wv.y, s);
            }
            #pragma unroll
            for (int d = 16; d > 0; d >>= 1)
                s += __shfl_xor_sync(0xffffffffu, s, d);
            if (lane == 0)
                out[(size_t)b * OO + o] = s + fc_b[o];
        }
    }
}

extern "C" void kernel_launch(void* const* d_in, const int* in_sizes, int n_in,
                              void* d_out, int out_size)
{
    const float* x    = (const float*)d_in[0];
    const float* W_ih = (const float*)d_in[1];
    const float* W_hh = (const float*)d_in[2];
    const float* b_ih = (const float*)d_in[3];
    const float* b_hh = (const float*)d_in[4];
    const float* fc_w = (const float*)d_in[5];
    const float* fc_b = (const float*)d_in[6];
    int nb = 0;
    for (int i = 0; i < n_in; ++i) {
        const float* p = (const float*)d_in[i];
        switch (in_sizes[i]) {
            case BB * TT * II: x    = p; break;
            case HH * II:      W_ih = p; break;
            case HH * HH:      W_hh = p; break;
            case OO * HH:      fc_w = p; break;
            case OO:           fc_b = p; break;
            case HH:           if (nb++ == 0) b_ih = p; else b_hh = p; break;
            default: break;
        }
    }
    float* out = (float*)d_out;

    cudaFuncSetAttribute(rnn_persistent_kernel,
                         cudaFuncAttributeMaxDynamicSharedMemorySize, SMEM_BYTES);
    rnn_persistent_kernel<<<NBLOCKS, NTHREADS, SMEM_BYTES>>>(
        x, W_ih, W_hh, b_ih, b_hh, fc_w, fc_b, out);
}